// round 7
// baseline (speedup 1.0000x reference)
#include <cuda_runtime.h>
#include <cuda_bf16.h>
#include <mma.h>
#include <cstdint>

using namespace nvcuda;

#define N_NODES 50000
#define N_EDGES 640000
#define D 128
#define KTOT 384          // concat width: [nfeats | sum_n/c | sum_e/c]
#define M_PAD 50048       // 391 * 128, GEMM M padding
#define NBLK_SCAN 49      // ceil(50000 / 1024)

#define BK 32             // K chunk
#define ASTR 40           // smem operand stride (bf16 elems) -> 80B, conflict-free ldmatrix
#define CSTR 132          // smem C stride (f32)
#define SMEM_BYTES (128 * CSTR * 4)   // 67584; operands need 4*128*40*2 = 40960

// ---------------- scratch (static __device__ globals; no allocs) -------------
__device__ int   g_cnt[N_NODES];
__device__ int   g_off[N_NODES + 1];
__device__ int   g_cur[N_NODES];
__device__ int   g_eid[N_EDGES];
__device__ int   g_bsum[64];
__device__ int   g_bpre[64];
__device__ float g_flag[N_NODES];         // 1.0 if node has >=1 in-edge
__device__ float g_bias2[D];              // Wa2 @ b_msg
// bf16 two-term split operands for the tensor-core GEMM
__device__ __nv_bfloat16 g_Ahi[(size_t)M_PAD * KTOT];  // pad rows stay 0 (.bss)
__device__ __nv_bfloat16 g_Alo[(size_t)M_PAD * KTOT];
__device__ __nv_bfloat16 g_Bhi[D * KTOT];              // [n][k] K-major
__device__ __nv_bfloat16 g_Blo[D * KTOT];

// ---------------- bf16 split helpers ----------------------------------------
__device__ __forceinline__ uint2 pack_bf4(float a, float b, float c, float d) {
    __nv_bfloat162 p0 = __floats2bfloat162_rn(a, b);
    __nv_bfloat162 p1 = __floats2bfloat162_rn(c, d);
    uint2 r;
    r.x = *(unsigned*)&p0;
    r.y = *(unsigned*)&p1;
    return r;
}
__device__ __forceinline__ float bf_res(float x) {   // residual after bf16 round
    return x - __bfloat162float(__float2bfloat16_rn(x));
}

// ---------------- K0: zero counts -------------------------------------------
__global__ void zero_kernel() {
    int i = blockIdx.x * blockDim.x + threadIdx.x;
    if (i < N_NODES) g_cnt[i] = 0;
}

// ---------------- K1: weight composition -> bf16 hi/lo B --------------------
// B[n][k]: k<128 -> Wa[n][k]; k>=128 -> sum_j Wa[n][128+j]*Wm[j][k-128]
__global__ void wc_kernel(const float* __restrict__ Wm,
                          const float* __restrict__ bm,
                          const float* __restrict__ Wa) {
    __shared__ float wa2[128];
    int o = blockIdx.x;           // 0..127 (output col n)
    int t = threadIdx.x;          // 0..255
    if (t < 128) wa2[t] = Wa[o * 256 + 128 + t];
    __syncthreads();
    if (t < 128) {
        float v = Wa[o * 256 + t];
        g_Bhi[o * KTOT + t] = __float2bfloat16_rn(v);
        g_Blo[o * KTOT + t] = __float2bfloat16_rn(bf_res(v));
    }
    float s = 0.f;
#pragma unroll 4
    for (int j = 0; j < 128; j++) s += wa2[j] * Wm[j * 256 + t];
    g_Bhi[o * KTOT + 128 + t] = __float2bfloat16_rn(s);
    g_Blo[o * KTOT + 128 + t] = __float2bfloat16_rn(bf_res(s));
    if (t == 0) {
        float b = 0.f;
        for (int j = 0; j < 128; j++) b += wa2[j] * bm[j];
        g_bias2[o] = b;
    }
}

// ---------------- K2: histogram dst -----------------------------------------
__global__ void count_kernel(const int* __restrict__ dst) {
    int i = blockIdx.x * blockDim.x + threadIdx.x;
    if (i < N_EDGES) atomicAdd(&g_cnt[dst[i]], 1);
}

// ---------------- K3a: per-block scan (49 blocks x 1024) --------------------
__global__ void scan1_kernel() {
    __shared__ int wsum[32];
    int t = threadIdx.x;
    int i = blockIdx.x * 1024 + t;
    int v = (i < N_NODES) ? g_cnt[i] : 0;
    int x = v;
#pragma unroll
    for (int o = 1; o < 32; o <<= 1) {
        int y = __shfl_up_sync(0xFFFFFFFFu, x, o);
        if ((t & 31) >= o) x += y;
    }
    if ((t & 31) == 31) wsum[t >> 5] = x;
    __syncthreads();
    if (t < 32) {
        int w = wsum[t];
#pragma unroll
        for (int o = 1; o < 32; o <<= 1) {
            int y = __shfl_up_sync(0xFFFFFFFFu, w, o);
            if (t >= o) w += y;
        }
        wsum[t] = w;
    }
    __syncthreads();
    int warp = t >> 5;
    int excl = x - v + (warp ? wsum[warp - 1] : 0);
    if (i < N_NODES) g_off[i] = excl;
    if (t == 1023) g_bsum[blockIdx.x] = wsum[31];
}

// ---------------- K3b: scan the 49 block sums (1 warp) ----------------------
__global__ void scan2_kernel() {
    int t = threadIdx.x;
    int a = g_bsum[t];
    int b = (32 + t < NBLK_SCAN) ? g_bsum[32 + t] : 0;
    int ia = a, ib = b;
#pragma unroll
    for (int o = 1; o < 32; o <<= 1) {
        int ya = __shfl_up_sync(0xFFFFFFFFu, ia, o);
        int yb = __shfl_up_sync(0xFFFFFFFFu, ib, o);
        if (t >= o) { ia += ya; ib += yb; }
    }
    int tot = __shfl_sync(0xFFFFFFFFu, ia, 31);
    g_bpre[t] = ia - a;
    if (32 + t < NBLK_SCAN) g_bpre[32 + t] = tot + ib - b;
}

// ---------------- K3c: add block prefixes, init cursors ---------------------
__global__ void scan3_kernel() {
    int i = blockIdx.x * blockDim.x + threadIdx.x;
    if (i < N_NODES) {
        int o = g_off[i] + g_bpre[i >> 10];
        g_off[i] = o;
        g_cur[i] = o;
    }
    if (i == 0) g_off[N_NODES] = N_EDGES;
}

// ---------------- K4: fill CSR edge lists -----------------------------------
__global__ void fill_kernel(const int* __restrict__ dst) {
    int i = blockIdx.x * blockDim.x + threadIdx.x;
    if (i < N_EDGES) {
        int v = dst[i];
        int p = atomicAdd(&g_cur[v], 1);
        g_eid[p] = i;
    }
}

// ---------------- K5: warp-per-node gather-sum -> bf16 hi/lo A --------------
__global__ void gather_kernel(const float* __restrict__ nfeats,
                              const float* __restrict__ efeats,
                              const int* __restrict__ src) {
    int node = (blockIdx.x * blockDim.x + threadIdx.x) >> 5;
    int lane = threadIdx.x & 31;
    if (node >= N_NODES) return;
    int s = g_off[node];
    int e = g_off[node + 1];
    float4 an = make_float4(0.f, 0.f, 0.f, 0.f);
    float4 ae = make_float4(0.f, 0.f, 0.f, 0.f);
    for (int p = s; p < e; p++) {
        int eid = g_eid[p];
        int sv  = __ldg(&src[eid]);
        float4 nv = ((const float4*)(nfeats + (size_t)sv * D))[lane];           // L2-resident
        float4 ev = __ldcs(((const float4*)(efeats + (size_t)eid * D)) + lane); // stream
        an.x += nv.x; an.y += nv.y; an.z += nv.z; an.w += nv.w;
        ae.x += ev.x; ae.y += ev.y; ae.z += ev.z; ae.w += ev.w;
    }
    float inv = 1.0f / (float)max(e - s, 1);
    an.x *= inv; an.y *= inv; an.z *= inv; an.w *= inv;
    ae.x *= inv; ae.y *= inv; ae.z *= inv; ae.w *= inv;
    float4 nf = ((const float4*)(nfeats + (size_t)node * D))[lane];

    size_t base = (size_t)node * KTOT + lane * 4;
    float4 segs[3] = { nf, an, ae };
#pragma unroll
    for (int sgi = 0; sgi < 3; sgi++) {
        float4 v = segs[sgi];
        *(uint2*)(g_Ahi + base + sgi * 128) = pack_bf4(v.x, v.y, v.z, v.w);
        *(uint2*)(g_Alo + base + sgi * 128) =
            pack_bf4(bf_res(v.x), bf_res(v.y), bf_res(v.z), bf_res(v.w));
    }
    if (lane == 0) g_flag[node] = (e > s) ? 1.0f : 0.0f;
}

// ---------------- K6: wmma bf16-split GEMM + epilogue -----------------------
// CTA = 128x128 tile, 8 warps (4x2), warp tile 32x64 = 2x4 wmma 16x16 frags.
// out = relu(A[128x384] @ B^T + bias), A = Ahi+Alo, B = Bhi+Blo (drop lo*lo).
__global__ __launch_bounds__(256, 2) void gemm_wmma_kernel(const float* __restrict__ bias_a,
                                                           float* __restrict__ out) {
    extern __shared__ char smem[];
    __nv_bfloat16* sAhi = (__nv_bfloat16*)smem;
    __nv_bfloat16* sAlo = sAhi + 128 * ASTR;
    __nv_bfloat16* sBhi = sAlo + 128 * ASTR;
    __nv_bfloat16* sBlo = sBhi + 128 * ASTR;
    float* sC = (float*)smem;

    const int tid = threadIdx.x;
    const int wid = tid >> 5;
    const int wr  = wid >> 1;       // 0..3 -> rows wr*32..+31
    const int wc  = wid & 1;        // 0..1 -> cols wc*64..+63
    const int m0  = blockIdx.x * 128;

    wmma::fragment<wmma::accumulator, 16, 16, 16, float> c[2][4];
#pragma unroll
    for (int mi = 0; mi < 2; mi++)
#pragma unroll
        for (int ni = 0; ni < 4; ni++) wmma::fill_fragment(c[mi][ni], 0.f);

    const int lrow = tid >> 2;            // 0..63  (fills 2 rows per iter pair)
    const int lg   = (tid & 3) * 8;       // bf16 granule offset

    for (int kc = 0; kc < KTOT; kc += BK) {
        __syncthreads();
        // fill operands: 4 tiles of 128x32 bf16, 16B per thread x 2 iters each
#pragma unroll
        for (int half = 0; half < 2; half++) {
            int row = lrow + half * 64;
            size_t ga = (size_t)(m0 + row) * KTOT + kc + lg;
            size_t gb = (size_t)row * KTOT + kc + lg;
            *(uint4*)(sAhi + row * ASTR + lg) = *(const uint4*)(g_Ahi + ga);
            *(uint4*)(sAlo + row * ASTR + lg) = *(const uint4*)(g_Alo + ga);
            *(uint4*)(sBhi + row * ASTR + lg) = *(const uint4*)(g_Bhi + gb);
            *(uint4*)(sBlo + row * ASTR + lg) = *(const uint4*)(g_Blo + gb);
        }
        __syncthreads();
#pragma unroll
        for (int ks = 0; ks < BK / 16; ks++) {
            wmma::fragment<wmma::matrix_a, 16, 16, 16, __nv_bfloat16, wmma::row_major> ah[2], al[2];
#pragma unroll
            for (int mi = 0; mi < 2; mi++) {
                const __nv_bfloat16* pa = sAhi + (wr * 32 + mi * 16) * ASTR + ks * 16;
                const __nv_bfloat16* pl = sAlo + (wr * 32 + mi * 16) * ASTR + ks * 16;
                wmma::load_matrix_sync(ah[mi], pa, ASTR);
                wmma::load_matrix_sync(al[mi], pl, ASTR);
            }
#pragma unroll
            for (int ni = 0; ni < 4; ni++) {
                wmma::fragment<wmma::matrix_b, 16, 16, 16, __nv_bfloat16, wmma::col_major> bh, bl;
                const __nv_bfloat16* pbh = sBhi + (wc * 64 + ni * 16) * ASTR + ks * 16;
                const __nv_bfloat16* pbl = sBlo + (wc * 64 + ni * 16) * ASTR + ks * 16;
                wmma::load_matrix_sync(bh, pbh, ASTR);
                wmma::load_matrix_sync(bl, pbl, ASTR);
#pragma unroll
                for (int mi = 0; mi < 2; mi++) {
                    wmma::mma_sync(c[mi][ni], ah[mi], bh, c[mi][ni]);
                    wmma::mma_sync(c[mi][ni], ah[mi], bl, c[mi][ni]);
                    wmma::mma_sync(c[mi][ni], al[mi], bh, c[mi][ni]);
                }
            }
        }
    }

    __syncthreads();   // operands dead; reuse smem for C
#pragma unroll
    for (int mi = 0; mi < 2; mi++)
#pragma unroll
        for (int ni = 0; ni < 4; ni++)
            wmma::store_matrix_sync(sC + (wr * 32 + mi * 16) * CSTR + wc * 64 + ni * 16,
                                    c[mi][ni], CSTR, wmma::mem_row_major);
    __syncthreads();

    // epilogue: relu(c + bias_a[n] + flag[m]*bias2[n]); thread = (row, 64-col half)
    {
        int row = tid >> 1;
        int ch  = (tid & 1) * 64;
        int m   = m0 + row;
        if (m < N_NODES) {
            float fl = g_flag[m];
            const float* crow = sC + row * CSTR + ch;
#pragma unroll
            for (int c4 = 0; c4 < 64; c4 += 4) {
                int col = ch + c4;
                float4 v = *(const float4*)(crow + c4);
                float v0 = v.x + __ldg(&bias_a[col + 0]) + fl * g_bias2[col + 0];
                float v1 = v.y + __ldg(&bias_a[col + 1]) + fl * g_bias2[col + 1];
                float v2 = v.z + __ldg(&bias_a[col + 2]) + fl * g_bias2[col + 2];
                float v3 = v.w + __ldg(&bias_a[col + 3]) + fl * g_bias2[col + 3];
                float4 o4;
                o4.x = v0 > 0.f ? v0 : 0.f;
                o4.y = v1 > 0.f ? v1 : 0.f;
                o4.z = v2 > 0.f ? v2 : 0.f;
                o4.w = v3 > 0.f ? v3 : 0.f;
                *(float4*)&out[(size_t)m * D + col] = o4;
            }
        }
    }
}

// ---------------- launch -----------------------------------------------------
extern "C" void kernel_launch(void* const* d_in, const int* in_sizes, int n_in,
                              void* d_out, int out_size) {
    const float* nfeats = (const float*)d_in[0];
    const float* efeats = (const float*)d_in[1];
    const float* Wm     = (const float*)d_in[2];
    const float* bm     = (const float*)d_in[3];
    const float* Wa     = (const float*)d_in[4];
    const float* ba     = (const float*)d_in[5];
    const int*   src    = (const int*)d_in[6];
    const int*   dst    = (const int*)d_in[7];
    float* out = (float*)d_out;

    cudaFuncSetAttribute(gemm_wmma_kernel,
                         cudaFuncAttributeMaxDynamicSharedMemorySize, SMEM_BYTES);

    zero_kernel  <<<(N_NODES + 255) / 256, 256>>>();
    wc_kernel    <<<D, 256>>>(Wm, bm, Wa);
    count_kernel <<<(N_EDGES + 255) / 256, 256>>>(dst);
    scan1_kernel <<<NBLK_SCAN, 1024>>>();
    scan2_kernel <<<1, 32>>>();
    scan3_kernel <<<(N_NODES + 255) / 256, 256>>>();
    fill_kernel  <<<(N_EDGES + 255) / 256, 256>>>(dst);
    gather_kernel<<<(N_NODES * 32 + 255) / 256, 256>>>(nfeats, efeats, src);
    gemm_wmma_kernel<<<M_PAD / 128, 256, SMEM_BYTES>>>(ba, out);
}

// round 10
// speedup vs baseline: 1.2787x; 1.2787x over previous
#include <cuda_runtime.h>
#include <cuda_bf16.h>
#include <mma.h>
#include <cstdint>

using namespace nvcuda;

#define N_NODES 50000
#define N_EDGES 640000
#define D 128
#define KTOT 384          // concat width: [nfeats | sum_n/c | sum_e/c]
#define M_PAD 50048       // 391 * 128, GEMM M padding
#define NBLK_SCAN 49      // ceil(50000 / 1024)

#define BK 32             // K chunk
#define ASTR 40           // smem operand stride (bf16 elems) -> 80B, conflict-free ldmatrix
#define CSTR 132          // smem C stride (f32)
#define SMEM_BYTES (128 * CSTR * 4)   // 67584; operands need 4*128*40*2 = 40960

// ---------------- scratch (static __device__ globals; no allocs) -------------
__device__ int   g_cnt[N_NODES];
__device__ int   g_off[N_NODES + 1];
__device__ int   g_cur[N_NODES];
__device__ int   g_eid[N_EDGES];
__device__ int   g_bsum[64];
__device__ int   g_bpre[64];
__device__ float g_flag[N_NODES];         // 1.0 if node has >=1 in-edge
__device__ float g_bias2[D];              // Wa2 @ b_msg
// bf16 two-term split operands for the tensor-core GEMM
__device__ __nv_bfloat16 g_Ahi[(size_t)M_PAD * KTOT];  // pad rows stay 0 (.bss)
__device__ __nv_bfloat16 g_Alo[(size_t)M_PAD * KTOT];
__device__ __nv_bfloat16 g_Bhi[D * KTOT];              // [n][k] K-major
__device__ __nv_bfloat16 g_Blo[D * KTOT];

// ---------------- bf16 split helpers ----------------------------------------
__device__ __forceinline__ uint2 pack_bf4(float a, float b, float c, float d) {
    __nv_bfloat162 p0 = __floats2bfloat162_rn(a, b);
    __nv_bfloat162 p1 = __floats2bfloat162_rn(c, d);
    uint2 r;
    r.x = *(unsigned*)&p0;
    r.y = *(unsigned*)&p1;
    return r;
}
__device__ __forceinline__ float bf_res(float x) {   // residual after bf16 round
    return x - __bfloat162float(__float2bfloat16_rn(x));
}

// ---------------- K0: zero counts -------------------------------------------
__global__ void zero_kernel() {
    int i = blockIdx.x * blockDim.x + threadIdx.x;
    if (i < N_NODES) g_cnt[i] = 0;
}

// ---------------- K1: weight composition -> bf16 hi/lo B --------------------
__global__ void wc_kernel(const float* __restrict__ Wm,
                          const float* __restrict__ bm,
                          const float* __restrict__ Wa) {
    __shared__ float wa2[128];
    int o = blockIdx.x;           // 0..127 (output col n)
    int t = threadIdx.x;          // 0..255
    if (t < 128) wa2[t] = Wa[o * 256 + 128 + t];
    __syncthreads();
    if (t < 128) {
        float v = Wa[o * 256 + t];
        g_Bhi[o * KTOT + t] = __float2bfloat16_rn(v);
        g_Blo[o * KTOT + t] = __float2bfloat16_rn(bf_res(v));
    }
    float s = 0.f;
#pragma unroll 4
    for (int j = 0; j < 128; j++) s += wa2[j] * Wm[j * 256 + t];
    g_Bhi[o * KTOT + 128 + t] = __float2bfloat16_rn(s);
    g_Blo[o * KTOT + 128 + t] = __float2bfloat16_rn(bf_res(s));
    if (t == 0) {
        float b = 0.f;
        for (int j = 0; j < 128; j++) b += wa2[j] * bm[j];
        g_bias2[o] = b;
    }
}

// ---------------- K2: histogram dst -----------------------------------------
__global__ void count_kernel(const int* __restrict__ dst) {
    int i = blockIdx.x * blockDim.x + threadIdx.x;
    if (i < N_EDGES) atomicAdd(&g_cnt[dst[i]], 1);
}

// ---------------- K3a: per-block scan (49 blocks x 1024) --------------------
__global__ void scan1_kernel() {
    __shared__ int wsum[32];
    int t = threadIdx.x;
    int i = blockIdx.x * 1024 + t;
    int v = (i < N_NODES) ? g_cnt[i] : 0;
    int x = v;
#pragma unroll
    for (int o = 1; o < 32; o <<= 1) {
        int y = __shfl_up_sync(0xFFFFFFFFu, x, o);
        if ((t & 31) >= o) x += y;
    }
    if ((t & 31) == 31) wsum[t >> 5] = x;
    __syncthreads();
    if (t < 32) {
        int w = wsum[t];
#pragma unroll
        for (int o = 1; o < 32; o <<= 1) {
            int y = __shfl_up_sync(0xFFFFFFFFu, w, o);
            if (t >= o) w += y;
        }
        wsum[t] = w;
    }
    __syncthreads();
    int warp = t >> 5;
    int excl = x - v + (warp ? wsum[warp - 1] : 0);
    if (i < N_NODES) g_off[i] = excl;
    if (t == 1023) g_bsum[blockIdx.x] = wsum[31];
}

// ---------------- K3b: scan the 49 block sums (1 warp) ----------------------
__global__ void scan2_kernel() {
    int t = threadIdx.x;
    int a = g_bsum[t];
    int b = (32 + t < NBLK_SCAN) ? g_bsum[32 + t] : 0;
    int ia = a, ib = b;
#pragma unroll
    for (int o = 1; o < 32; o <<= 1) {
        int ya = __shfl_up_sync(0xFFFFFFFFu, ia, o);
        int yb = __shfl_up_sync(0xFFFFFFFFu, ib, o);
        if (t >= o) { ia += ya; ib += yb; }
    }
    int tot = __shfl_sync(0xFFFFFFFFu, ia, 31);
    g_bpre[t] = ia - a;
    if (32 + t < NBLK_SCAN) g_bpre[32 + t] = tot + ib - b;
}

// ---------------- K3c: add block prefixes, init cursors ---------------------
__global__ void scan3_kernel() {
    int i = blockIdx.x * blockDim.x + threadIdx.x;
    if (i < N_NODES) {
        int o = g_off[i] + g_bpre[i >> 10];
        g_off[i] = o;
        g_cur[i] = o;
    }
    if (i == 0) g_off[N_NODES] = N_EDGES;
}

// ---------------- K4: fill CSR edge lists -----------------------------------
__global__ void fill_kernel(const int* __restrict__ dst) {
    int i = blockIdx.x * blockDim.x + threadIdx.x;
    if (i < N_EDGES) {
        int v = dst[i];
        int p = atomicAdd(&g_cur[v], 1);
        g_eid[p] = i;
    }
}

// ---------------- K5: gather-sum with lane-parallel index prefetch ----------
// Warp per node. Step 1: lanes cooperatively load up to 32 (eid, src) pairs in
// ONE parallel coalesced round (g_eid[s..e) is contiguous). Step 2: broadcast
// via shfl; feature loads now have register-resident addresses -> deep MLP.
__global__ void gather_kernel(const float* __restrict__ nfeats,
                              const float* __restrict__ efeats,
                              const int* __restrict__ src) {
    int node = (blockIdx.x * blockDim.x + threadIdx.x) >> 5;
    int lane = threadIdx.x & 31;
    if (node >= N_NODES) return;
    int s = g_off[node];
    int e = g_off[node + 1];
    float4 an = make_float4(0.f, 0.f, 0.f, 0.f);
    float4 ae = make_float4(0.f, 0.f, 0.f, 0.f);

    for (int base = s; base < e; base += 32) {
        int p = base + lane;
        int my_eid = 0, my_src = 0;
        if (p < e) {
            my_eid = g_eid[p];            // coalesced: consecutive lanes, consecutive p
            my_src = __ldg(&src[my_eid]); // parallel across lanes (1 chase, not deg chases)
        }
        int cnt = min(32, e - base);
#pragma unroll 4
        for (int j = 0; j < cnt; j++) {
            int eid_j = __shfl_sync(0xFFFFFFFFu, my_eid, j);
            int sv_j  = __shfl_sync(0xFFFFFFFFu, my_src, j);
            float4 nv = __ldg (((const float4*)(nfeats + (size_t)sv_j  * D)) + lane); // L2-resident
            float4 ev = __ldcs(((const float4*)(efeats + (size_t)eid_j * D)) + lane); // stream
            an.x += nv.x; an.y += nv.y; an.z += nv.z; an.w += nv.w;
            ae.x += ev.x; ae.y += ev.y; ae.z += ev.z; ae.w += ev.w;
        }
    }

    float inv = 1.0f / (float)max(e - s, 1);
    an.x *= inv; an.y *= inv; an.z *= inv; an.w *= inv;
    ae.x *= inv; ae.y *= inv; ae.z *= inv; ae.w *= inv;
    float4 nf = ((const float4*)(nfeats + (size_t)node * D))[lane];

    size_t base = (size_t)node * KTOT + lane * 4;
    float4 segs[3] = { nf, an, ae };
#pragma unroll
    for (int sgi = 0; sgi < 3; sgi++) {
        float4 v = segs[sgi];
        *(uint2*)(g_Ahi + base + sgi * 128) = pack_bf4(v.x, v.y, v.z, v.w);
        *(uint2*)(g_Alo + base + sgi * 128) =
            pack_bf4(bf_res(v.x), bf_res(v.y), bf_res(v.z), bf_res(v.w));
    }
    if (lane == 0) g_flag[node] = (e > s) ? 1.0f : 0.0f;
}

// ---------------- K6: wmma bf16-split GEMM + epilogue -----------------------
// CTA = 128x128 tile, 8 warps (4x2), warp tile 32x64 = 2x4 wmma 16x16 frags.
// out = relu(A[128x384] @ B^T + bias), A = Ahi+Alo, B = Bhi+Blo (drop lo*lo).
__global__ __launch_bounds__(256, 2) void gemm_wmma_kernel(const float* __restrict__ bias_a,
                                                           float* __restrict__ out) {
    extern __shared__ char smem[];
    __nv_bfloat16* sAhi = (__nv_bfloat16*)smem;
    __nv_bfloat16* sAlo = sAhi + 128 * ASTR;
    __nv_bfloat16* sBhi = sAlo + 128 * ASTR;
    __nv_bfloat16* sBlo = sBhi + 128 * ASTR;
    float* sC = (float*)smem;

    const int tid = threadIdx.x;
    const int wid = tid >> 5;
    const int wr  = wid >> 1;       // 0..3 -> rows wr*32..+31
    const int wc  = wid & 1;        // 0..1 -> cols wc*64..+63
    const int m0  = blockIdx.x * 128;

    wmma::fragment<wmma::accumulator, 16, 16, 16, float> c[2][4];
#pragma unroll
    for (int mi = 0; mi < 2; mi++)
#pragma unroll
        for (int ni = 0; ni < 4; ni++) wmma::fill_fragment(c[mi][ni], 0.f);

    const int lrow = tid >> 2;            // 0..63
    const int lg   = (tid & 3) * 8;       // bf16 granule offset

    for (int kc = 0; kc < KTOT; kc += BK) {
        __syncthreads();
#pragma unroll
        for (int half = 0; half < 2; half++) {
            int row = lrow + half * 64;
            size_t ga = (size_t)(m0 + row) * KTOT + kc + lg;
            size_t gb = (size_t)row * KTOT + kc + lg;
            *(uint4*)(sAhi + row * ASTR + lg) = *(const uint4*)(g_Ahi + ga);
            *(uint4*)(sAlo + row * ASTR + lg) = *(const uint4*)(g_Alo + ga);
            *(uint4*)(sBhi + row * ASTR + lg) = *(const uint4*)(g_Bhi + gb);
            *(uint4*)(sBlo + row * ASTR + lg) = *(const uint4*)(g_Blo + gb);
        }
        __syncthreads();
#pragma unroll
        for (int ks = 0; ks < BK / 16; ks++) {
            wmma::fragment<wmma::matrix_a, 16, 16, 16, __nv_bfloat16, wmma::row_major> ah[2], al[2];
#pragma unroll
            for (int mi = 0; mi < 2; mi++) {
                const __nv_bfloat16* pa = sAhi + (wr * 32 + mi * 16) * ASTR + ks * 16;
                const __nv_bfloat16* pl = sAlo + (wr * 32 + mi * 16) * ASTR + ks * 16;
                wmma::load_matrix_sync(ah[mi], pa, ASTR);
                wmma::load_matrix_sync(al[mi], pl, ASTR);
            }
#pragma unroll
            for (int ni = 0; ni < 4; ni++) {
                wmma::fragment<wmma::matrix_b, 16, 16, 16, __nv_bfloat16, wmma::col_major> bh, bl;
                const __nv_bfloat16* pbh = sBhi + (wc * 64 + ni * 16) * ASTR + ks * 16;
                const __nv_bfloat16* pbl = sBlo + (wc * 64 + ni * 16) * ASTR + ks * 16;
                wmma::load_matrix_sync(bh, pbh, ASTR);
                wmma::load_matrix_sync(bl, pbl, ASTR);
#pragma unroll
                for (int mi = 0; mi < 2; mi++) {
                    wmma::mma_sync(c[mi][ni], ah[mi], bh, c[mi][ni]);
                    wmma::mma_sync(c[mi][ni], ah[mi], bl, c[mi][ni]);
                    wmma::mma_sync(c[mi][ni], al[mi], bh, c[mi][ni]);
                }
            }
        }
    }

    __syncthreads();   // operands dead; reuse smem for C
#pragma unroll
    for (int mi = 0; mi < 2; mi++)
#pragma unroll
        for (int ni = 0; ni < 4; ni++)
            wmma::store_matrix_sync(sC + (wr * 32 + mi * 16) * CSTR + wc * 64 + ni * 16,
                                    c[mi][ni], CSTR, wmma::mem_row_major);
    __syncthreads();

    // epilogue: relu(c + bias_a[n] + flag[m]*bias2[n]); thread = (row, 64-col half)
    {
        int row = tid >> 1;
        int ch  = (tid & 1) * 64;
        int m   = m0 + row;
        if (m < N_NODES) {
            float fl = g_flag[m];
            const float* crow = sC + row * CSTR + ch;
#pragma unroll
            for (int c4 = 0; c4 < 64; c4 += 4) {
                int col = ch + c4;
                float4 v = *(const float4*)(crow + c4);
                float v0 = v.x + __ldg(&bias_a[col + 0]) + fl * g_bias2[col + 0];
                float v1 = v.y + __ldg(&bias_a[col + 1]) + fl * g_bias2[col + 1];
                float v2 = v.z + __ldg(&bias_a[col + 2]) + fl * g_bias2[col + 2];
                float v3 = v.w + __ldg(&bias_a[col + 3]) + fl * g_bias2[col + 3];
                float4 o4;
                o4.x = v0 > 0.f ? v0 : 0.f;
                o4.y = v1 > 0.f ? v1 : 0.f;
                o4.z = v2 > 0.f ? v2 : 0.f;
                o4.w = v3 > 0.f ? v3 : 0.f;
                *(float4*)&out[(size_t)m * D + col] = o4;
            }
        }
    }
}

// ---------------- launch -----------------------------------------------------
extern "C" void kernel_launch(void* const* d_in, const int* in_sizes, int n_in,
                              void* d_out, int out_size) {
    const float* nfeats = (const float*)d_in[0];
    const float* efeats = (const float*)d_in[1];
    const float* Wm     = (const float*)d_in[2];
    const float* bm     = (const float*)d_in[3];
    const float* Wa     = (const float*)d_in[4];
    const float* ba     = (const float*)d_in[5];
    const int*   src    = (const int*)d_in[6];
    const int*   dst    = (const int*)d_in[7];
    float* out = (float*)d_out;

    cudaFuncSetAttribute(gemm_wmma_kernel,
                         cudaFuncAttributeMaxDynamicSharedMemorySize, SMEM_BYTES);

    zero_kernel  <<<(N_NODES + 255) / 256, 256>>>();
    wc_kernel    <<<D, 256>>>(Wm, bm, Wa);
    count_kernel <<<(N_EDGES + 255) / 256, 256>>>(dst);
    scan1_kernel <<<NBLK_SCAN, 1024>>>();
    scan2_kernel <<<1, 32>>>();
    scan3_kernel <<<(N_NODES + 255) / 256, 256>>>();
    fill_kernel  <<<(N_EDGES + 255) / 256, 256>>>(dst);
    gather_kernel<<<(N_NODES * 32 + 255) / 256, 256>>>(nfeats, efeats, src);
    gemm_wmma_kernel<<<M_PAD / 128, 256, SMEM_BYTES>>>(ba, out);
}

// round 12
// speedup vs baseline: 1.3849x; 1.0830x over previous
#include <cuda_runtime.h>
#include <cuda_bf16.h>
#include <mma.h>
#include <cstdint>

using namespace nvcuda;

#define N_NODES 50000
#define N_EDGES 640000
#define D 128
#define KTOT 384          // concat width: [nfeats | sum_n/c | sum_e/c]
#define M_PAD 50048       // 391 * 128, GEMM M padding
#define NBLK_SCAN 49      // ceil(50000 / 1024)

#define BK 32             // K chunk
#define ASTR 40           // smem operand stride (bf16 elems) -> 80B, conflict-free ldmatrix
#define CSTR 132          // smem C stride (f32)
// double-buffered operand stages: 4 ops x 128 x ASTR x 2B = 40960 per stage
#define OPB   (128 * ASTR * 2)
#define STAGE (4 * OPB)
#define SMEM_BYTES (2 * STAGE)        // 81920 >= C reuse (128*CSTR*4 = 67584)

// ---------------- scratch (static __device__ globals; no allocs) -------------
__device__ int   g_cnt[N_NODES];      // .bss zero; self-cleaned by scan3 each run
__device__ int   g_off[N_NODES + 1];
__device__ int   g_cur[N_NODES];
__device__ int   g_eid[N_EDGES];
__device__ int   g_bsum[64];
__device__ int   g_bpre[64];
__device__ float g_flag[N_NODES];     // 1.0 if node has >=1 in-edge
__device__ float g_bias2[D];          // Wa2 @ b_msg
// bf16 two-term split operands for the tensor-core GEMM
__device__ __nv_bfloat16 g_Ahi[(size_t)M_PAD * KTOT];  // pad rows stay 0 (.bss)
__device__ __nv_bfloat16 g_Alo[(size_t)M_PAD * KTOT];
__device__ __nv_bfloat16 g_Bhi[D * KTOT];              // [n][k] K-major
__device__ __nv_bfloat16 g_Blo[D * KTOT];

// ---------------- bf16 split helpers ----------------------------------------
__device__ __forceinline__ uint2 pack_bf4(float a, float b, float c, float d) {
    __nv_bfloat162 p0 = __floats2bfloat162_rn(a, b);
    __nv_bfloat162 p1 = __floats2bfloat162_rn(c, d);
    uint2 r;
    r.x = *(unsigned*)&p0;
    r.y = *(unsigned*)&p1;
    return r;
}
__device__ __forceinline__ float bf_res(float x) {   // residual after bf16 round
    return x - __bfloat162float(__float2bfloat16_rn(x));
}

// ---------------- cp.async helpers ------------------------------------------
__device__ __forceinline__ void cp16(void* dst_smem, const void* src) {
    uint32_t s = (uint32_t)__cvta_generic_to_shared(dst_smem);
    asm volatile("cp.async.ca.shared.global [%0], [%1], 16;" :: "r"(s), "l"(src));
}
__device__ __forceinline__ void cp_commit() { asm volatile("cp.async.commit_group;" ::: "memory"); }
__device__ __forceinline__ void cp_wait1()  { asm volatile("cp.async.wait_group 1;" ::: "memory"); }
__device__ __forceinline__ void cp_wait0()  { asm volatile("cp.async.wait_group 0;" ::: "memory"); }

// ---------------- K1: weight composition -> bf16 hi/lo B --------------------
__global__ void wc_kernel(const float* __restrict__ Wm,
                          const float* __restrict__ bm,
                          const float* __restrict__ Wa) {
    __shared__ float wa2[128];
    int o = blockIdx.x;           // 0..127 (output col n)
    int t = threadIdx.x;          // 0..255
    if (t < 128) wa2[t] = Wa[o * 256 + 128 + t];
    __syncthreads();
    if (t < 128) {
        float v = Wa[o * 256 + t];
        g_Bhi[o * KTOT + t] = __float2bfloat16_rn(v);
        g_Blo[o * KTOT + t] = __float2bfloat16_rn(bf_res(v));
    }
    float s = 0.f;
#pragma unroll 4
    for (int j = 0; j < 128; j++) s += wa2[j] * Wm[j * 256 + t];
    g_Bhi[o * KTOT + 128 + t] = __float2bfloat16_rn(s);
    g_Blo[o * KTOT + 128 + t] = __float2bfloat16_rn(bf_res(s));
    if (t == 0) {
        float b = 0.f;
        for (int j = 0; j < 128; j++) b += wa2[j] * bm[j];
        g_bias2[o] = b;
    }
}

// ---------------- K2: histogram dst (g_cnt is pre-zeroed invariant) ---------
__global__ void count_kernel(const int* __restrict__ dst) {
    int i = blockIdx.x * blockDim.x + threadIdx.x;
    if (i < N_EDGES) atomicAdd(&g_cnt[dst[i]], 1);
}

// ---------------- K3a: per-block scan (49 blocks x 1024) --------------------
__global__ void scan1_kernel() {
    __shared__ int wsum[32];
    int t = threadIdx.x;
    int i = blockIdx.x * 1024 + t;
    int v = (i < N_NODES) ? g_cnt[i] : 0;
    int x = v;
#pragma unroll
    for (int o = 1; o < 32; o <<= 1) {
        int y = __shfl_up_sync(0xFFFFFFFFu, x, o);
        if ((t & 31) >= o) x += y;
    }
    if ((t & 31) == 31) wsum[t >> 5] = x;
    __syncthreads();
    if (t < 32) {
        int w = wsum[t];
#pragma unroll
        for (int o = 1; o < 32; o <<= 1) {
            int y = __shfl_up_sync(0xFFFFFFFFu, w, o);
            if (t >= o) w += y;
        }
        wsum[t] = w;
    }
    __syncthreads();
    int warp = t >> 5;
    int excl = x - v + (warp ? wsum[warp - 1] : 0);
    if (i < N_NODES) g_off[i] = excl;
    if (t == 1023) g_bsum[blockIdx.x] = wsum[31];
}

// ---------------- K3b: scan the 49 block sums (1 warp) ----------------------
__global__ void scan2_kernel() {
    int t = threadIdx.x;
    int a = g_bsum[t];
    int b = (32 + t < NBLK_SCAN) ? g_bsum[32 + t] : 0;
    int ia = a, ib = b;
#pragma unroll
    for (int o = 1; o < 32; o <<= 1) {
        int ya = __shfl_up_sync(0xFFFFFFFFu, ia, o);
        int yb = __shfl_up_sync(0xFFFFFFFFu, ib, o);
        if (t >= o) { ia += ya; ib += yb; }
    }
    int tot = __shfl_sync(0xFFFFFFFFu, ia, 31);
    g_bpre[t] = ia - a;
    if (32 + t < NBLK_SCAN) g_bpre[32 + t] = tot + ib - b;
}

// ---------------- K3c: add prefixes, init cursors, SELF-CLEAN g_cnt ---------
__global__ void scan3_kernel() {
    int i = blockIdx.x * blockDim.x + threadIdx.x;
    if (i < N_NODES) {
        int o = g_off[i] + g_bpre[i >> 10];
        g_off[i] = o;
        g_cur[i] = o;
        g_cnt[i] = 0;              // restore the zero invariant for the next run
    }
    if (i == 0) g_off[N_NODES] = N_EDGES;
}

// ---------------- K4: fill CSR edge lists -----------------------------------
__global__ void fill_kernel(const int* __restrict__ dst) {
    int i = blockIdx.x * blockDim.x + threadIdx.x;
    if (i < N_EDGES) {
        int v = dst[i];
        int p = atomicAdd(&g_cur[v], 1);
        g_eid[p] = i;
    }
}

// ---------------- K5: gather-sum with lane-parallel index prefetch ----------
__global__ void gather_kernel(const float* __restrict__ nfeats,
                              const float* __restrict__ efeats,
                              const int* __restrict__ src) {
    int node = (blockIdx.x * blockDim.x + threadIdx.x) >> 5;
    int lane = threadIdx.x & 31;
    if (node >= N_NODES) return;
    int s = g_off[node];
    int e = g_off[node + 1];
    float4 an = make_float4(0.f, 0.f, 0.f, 0.f);
    float4 ae = make_float4(0.f, 0.f, 0.f, 0.f);

    for (int base = s; base < e; base += 32) {
        int p = base + lane;
        int my_eid = 0, my_src = 0;
        if (p < e) {
            my_eid = g_eid[p];            // coalesced: consecutive lanes, consecutive p
            my_src = __ldg(&src[my_eid]); // parallel across lanes
        }
        int cnt = min(32, e - base);
#pragma unroll 8
        for (int j = 0; j < cnt; j++) {
            int eid_j = __shfl_sync(0xFFFFFFFFu, my_eid, j);
            int sv_j  = __shfl_sync(0xFFFFFFFFu, my_src, j);
            float4 nv = __ldg (((const float4*)(nfeats + (size_t)sv_j  * D)) + lane); // L2-resident
            float4 ev = __ldcs(((const float4*)(efeats + (size_t)eid_j * D)) + lane); // stream
            an.x += nv.x; an.y += nv.y; an.z += nv.z; an.w += nv.w;
            ae.x += ev.x; ae.y += ev.y; ae.z += ev.z; ae.w += ev.w;
        }
    }

    float inv = 1.0f / (float)max(e - s, 1);
    an.x *= inv; an.y *= inv; an.z *= inv; an.w *= inv;
    ae.x *= inv; ae.y *= inv; ae.z *= inv; ae.w *= inv;
    float4 nf = ((const float4*)(nfeats + (size_t)node * D))[lane];

    size_t base = (size_t)node * KTOT + lane * 4;
    float4 segs[3] = { nf, an, ae };
#pragma unroll
    for (int sgi = 0; sgi < 3; sgi++) {
        float4 v = segs[sgi];
        *(uint2*)(g_Ahi + base + sgi * 128) = pack_bf4(v.x, v.y, v.z, v.w);
        *(uint2*)(g_Alo + base + sgi * 128) =
            pack_bf4(bf_res(v.x), bf_res(v.y), bf_res(v.z), bf_res(v.w));
    }
    if (lane == 0) g_flag[node] = (e > s) ? 1.0f : 0.0f;
}

// ---------------- K6: wmma bf16-split GEMM, cp.async double-buffered --------
// CTA = 128x128 tile, 8 warps (4x2), warp tile 32x64 = 2x4 wmma 16x16 frags.
__global__ __launch_bounds__(256, 2) void gemm_wmma_kernel(const float* __restrict__ bias_a,
                                                           float* __restrict__ out) {
    extern __shared__ char smem[];
    float* sC = (float*)smem;

    const int tid = threadIdx.x;
    const int wid = tid >> 5;
    const int wr  = wid >> 1;       // 0..3 -> rows wr*32..+31
    const int wc  = wid & 1;        // 0..1 -> cols wc*64..+63
    const int m0  = blockIdx.x * 128;

    const int lrow = tid >> 2;            // 0..63
    const int lg   = (tid & 3) * 8;       // bf16 granule offset

    // async-load one BK chunk (4 operand tiles) into a stage
    auto load_chunk = [&](int kc, int stage) {
        char* sb = smem + stage * STAGE;
#pragma unroll
        for (int half = 0; half < 2; half++) {
            int row = lrow + half * 64;
            size_t ga = (size_t)(m0 + row) * KTOT + kc + lg;
            size_t gb = (size_t)row * KTOT + kc + lg;
            uint32_t so = (row * ASTR + lg) * 2;
            cp16(sb + 0 * OPB + so, g_Ahi + ga);
            cp16(sb + 1 * OPB + so, g_Alo + ga);
            cp16(sb + 2 * OPB + so, g_Bhi + gb);
            cp16(sb + 3 * OPB + so, g_Blo + gb);
        }
        cp_commit();
    };

    wmma::fragment<wmma::accumulator, 16, 16, 16, float> c[2][4];
#pragma unroll
    for (int mi = 0; mi < 2; mi++)
#pragma unroll
        for (int ni = 0; ni < 4; ni++) wmma::fill_fragment(c[mi][ni], 0.f);

    load_chunk(0, 0);

    const int NCH = KTOT / BK;      // 12
#pragma unroll 1
    for (int i = 0; i < NCH; i++) {
        if (i + 1 < NCH) { load_chunk((i + 1) * BK, (i + 1) & 1); cp_wait1(); }
        else             { cp_wait0(); }
        __syncthreads();

        char* sb = smem + (i & 1) * STAGE;
        __nv_bfloat16* sAhi = (__nv_bfloat16*)(sb + 0 * OPB);
        __nv_bfloat16* sAlo = (__nv_bfloat16*)(sb + 1 * OPB);
        __nv_bfloat16* sBhi = (__nv_bfloat16*)(sb + 2 * OPB);
        __nv_bfloat16* sBlo = (__nv_bfloat16*)(sb + 3 * OPB);

#pragma unroll
        for (int ks = 0; ks < BK / 16; ks++) {
            wmma::fragment<wmma::matrix_a, 16, 16, 16, __nv_bfloat16, wmma::row_major> ah[2], al[2];
#pragma unroll
            for (int mi = 0; mi < 2; mi++) {
                wmma::load_matrix_sync(ah[mi], sAhi + (wr * 32 + mi * 16) * ASTR + ks * 16, ASTR);
                wmma::load_matrix_sync(al[mi], sAlo + (wr * 32 + mi * 16) * ASTR + ks * 16, ASTR);
            }
#pragma unroll
            for (int ni = 0; ni < 4; ni++) {
                wmma::fragment<wmma::matrix_b, 16, 16, 16, __nv_bfloat16, wmma::col_major> bh, bl;
                wmma::load_matrix_sync(bh, sBhi + (wc * 64 + ni * 16) * ASTR + ks * 16, ASTR);
                wmma::load_matrix_sync(bl, sBlo + (wc * 64 + ni * 16) * ASTR + ks * 16, ASTR);
#pragma unroll
                for (int mi = 0; mi < 2; mi++) {
                    wmma::mma_sync(c[mi][ni], ah[mi], bh, c[mi][ni]);
                    wmma::mma_sync(c[mi][ni], ah[mi], bl, c[mi][ni]);
                    wmma::mma_sync(c[mi][ni], al[mi], bh, c[mi][ni]);
                }
            }
        }
        __syncthreads();   // all warps done reading this stage before it is refilled
    }

    // operands dead; reuse smem for C
#pragma unroll
    for (int mi = 0; mi < 2; mi++)
#pragma unroll
        for (int ni = 0; ni < 4; ni++)
            wmma::store_matrix_sync(sC + (wr * 32 + mi * 16) * CSTR + wc * 64 + ni * 16,
                                    c[mi][ni], CSTR, wmma::mem_row_major);
    __syncthreads();

    // epilogue: relu(c + bias_a[n] + flag[m]*bias2[n]); thread = (row, 64-col half)
    {
        int row = tid >> 1;
        int ch  = (tid & 1) * 64;
        int m   = m0 + row;
        if (m < N_NODES) {
            float fl = g_flag[m];
            const float* crow = sC + row * CSTR + ch;
#pragma unroll
            for (int c4 = 0; c4 < 64; c4 += 4) {
                int col = ch + c4;
                float4 v = *(const float4*)(crow + c4);
                float v0 = v.x + __ldg(&bias_a[col + 0]) + fl * g_bias2[col + 0];
                float v1 = v.y + __ldg(&bias_a[col + 1]) + fl * g_bias2[col + 1];
                float v2 = v.z + __ldg(&bias_a[col + 2]) + fl * g_bias2[col + 2];
                float v3 = v.w + __ldg(&bias_a[col + 3]) + fl * g_bias2[col + 3];
                float4 o4;
                o4.x = v0 > 0.f ? v0 : 0.f;
                o4.y = v1 > 0.f ? v1 : 0.f;
                o4.z = v2 > 0.f ? v2 : 0.f;
                o4.w = v3 > 0.f ? v3 : 0.f;
                *(float4*)&out[(size_t)m * D + col] = o4;
            }
        }
    }
}

// ---------------- launch -----------------------------------------------------
extern "C" void kernel_launch(void* const* d_in, const int* in_sizes, int n_in,
                              void* d_out, int out_size) {
    const float* nfeats = (const float*)d_in[0];
    const float* efeats = (const float*)d_in[1];
    const float* Wm     = (const float*)d_in[2];
    const float* bm     = (const float*)d_in[3];
    const float* Wa     = (const float*)d_in[4];
    const float* ba     = (const float*)d_in[5];
    const int*   src    = (const int*)d_in[6];
    const int*   dst    = (const int*)d_in[7];
    float* out = (float*)d_out;

    cudaFuncSetAttribute(gemm_wmma_kernel,
                         cudaFuncAttributeMaxDynamicSharedMemorySize, SMEM_BYTES);

    wc_kernel    <<<D, 256>>>(Wm, bm, Wa);
    count_kernel <<<(N_EDGES + 255) / 256, 256>>>(dst);
    scan1_kernel <<<NBLK_SCAN, 1024>>>();
    scan2_kernel <<<1, 32>>>();
    scan3_kernel <<<(N_NODES + 255) / 256, 256>>>();
    fill_kernel  <<<(N_EDGES + 255) / 256, 256>>>(dst);
    gather_kernel<<<(N_NODES * 32 + 255) / 256, 256>>>(nfeats, efeats, src);
    gemm_wmma_kernel<<<M_PAD / 128, 256, SMEM_BYTES>>>(ba, out);
}